// round 6
// baseline (speedup 1.0000x reference)
#include <cuda_runtime.h>
#include <cuda_bf16.h>
#include <cstdint>
#include <cstddef>

#define NN 50000
#define NE 600000
#define DD 128
#define HH 256
#define TM 64

// ============================ device scratch ================================
__device__ float g_agg[(size_t)NN * DD];
// weights transposed to [N][K] row-major, bf16 hi/lo split
__device__ __nv_bfloat16 g_mW0h[HH * HH], g_mW0l[HH * HH];  // msg W0^T: [256][256]
__device__ __nv_bfloat16 g_mW1h[DD * HH], g_mW1l[DD * HH];  // msg W1^T: [128][256]
__device__ __nv_bfloat16 g_uW0h[HH * HH], g_uW0l[HH * HH];
__device__ __nv_bfloat16 g_uW1h[DD * HH], g_uW1l[DD * HH];

// ============================ smem layout (bytes) ===========================
// A tiles: 64 rows x 264 halves (528B stride = 33x16B -> conflict-free ldsm)
// B chunk: 128 N-rows x kc=32 K-cols, 80B stride; double-buffered hi/lo
#define SM_B0   0                       // 256 floats
#define SM_B1   1024                    // 128 floats
#define SM_FR   1536                    // 64 ints
#define SM_TO   1792                    // 64 ints
#define SM_AHI  4096
#define SM_ALO  (4096 + 33792)          // 37888
#define SM_B    (37888 + 33792)         // 71680
#define BROW    80
#define BHALF   10240                   // 128 rows * 80B
#define BBUF    20480                   // hi+lo per buffer
#define SMEM_TOTAL (71680 + 2 * BBUF)   // 112640  -> 2 CTAs/SM
#define AROW 528

// ============================ PTX helpers ===================================
__device__ __forceinline__ uint32_t smem_u32(const void* p) {
    uint32_t a;
    asm("{ .reg .u64 t; cvta.to.shared.u64 t, %1; cvt.u32.u64 %0, t; }" : "=r"(a) : "l"(p));
    return a;
}
__device__ __forceinline__ void ldsm_x4(uint32_t& r0, uint32_t& r1, uint32_t& r2,
                                        uint32_t& r3, uint32_t addr) {
    asm volatile("ldmatrix.sync.aligned.m8n8.x4.shared.b16 {%0,%1,%2,%3}, [%4];"
                 : "=r"(r0), "=r"(r1), "=r"(r2), "=r"(r3) : "r"(addr));
}
__device__ __forceinline__ void mma_bf16(float* d, const uint32_t* a,
                                         uint32_t b0, uint32_t b1) {
    asm volatile(
        "mma.sync.aligned.m16n8k16.row.col.f32.bf16.bf16.f32 "
        "{%0,%1,%2,%3},{%4,%5,%6,%7},{%8,%9},{%0,%1,%2,%3};"
        : "+f"(d[0]), "+f"(d[1]), "+f"(d[2]), "+f"(d[3])
        : "r"(a[0]), "r"(a[1]), "r"(a[2]), "r"(a[3]), "r"(b0), "r"(b1));
}
__device__ __forceinline__ uint32_t pack_bf16(float a, float b) {
    __nv_bfloat162 t = __floats2bfloat162_rn(a, b);
    return *reinterpret_cast<uint32_t*>(&t);
}
__device__ __forceinline__ void cpa16(uint32_t dst, const void* src) {
    asm volatile("cp.async.cg.shared.global [%0], [%1], 16;"
                 :: "r"(dst), "l"(src) : "memory");
}
#define CP_COMMIT() asm volatile("cp.async.commit_group;" ::: "memory")
#define CP_WAIT(n)  asm volatile("cp.async.wait_group %0;" :: "n"(n) : "memory")

// =========================== prelude kernels ================================
__global__ void zero_agg_kernel() {
    const size_t n4 = (size_t)NN * DD / 4;
    float4 z = make_float4(0.f, 0.f, 0.f, 0.f);
    for (size_t i = (size_t)blockIdx.x * blockDim.x + threadIdx.x; i < n4;
         i += (size_t)gridDim.x * blockDim.x)
        reinterpret_cast<float4*>(g_agg)[i] = z;
}

__device__ __forceinline__ void put_split(__nv_bfloat16* h, __nv_bfloat16* l,
                                          int idx, float w) {
    __nv_bfloat16 hi = __float2bfloat16(w);
    h[idx] = hi;
    l[idx] = __float2bfloat16(w - __bfloat162float(hi));
}

// W (row-major [K][N]) -> transposed [N][K] hi/lo
__global__ void conv_w_kernel(const float* __restrict__ mW0, const float* __restrict__ uW0,
                              const float* __restrict__ mW1, const float* __restrict__ uW1) {
    int i = blockIdx.x * blockDim.x + threadIdx.x;
    if (i >= 196608) return;
    if (i < 65536) {
        int k = i >> 8, n = i & 255;
        put_split(g_mW0h, g_mW0l, n * HH + k, mW0[i]);
    } else if (i < 131072) {
        int j = i - 65536, k = j >> 8, n = j & 255;
        put_split(g_uW0h, g_uW0l, n * HH + k, uW0[j]);
    } else if (i < 163840) {
        int j = i - 131072, k = j >> 7, n = j & 127;
        put_split(g_mW1h, g_mW1l, n * HH + k, mW1[j]);
    } else {
        int j = i - 163840, k = j >> 7, n = j & 127;
        put_split(g_uW1h, g_uW1l, n * HH + k, uW1[j]);
    }
}

// stage one 128-row x kc=32 chunk of W^T hi/lo into B buffer `buf` (256 thr)
__device__ __forceinline__ void stage_chunk(uint32_t sb, int tid, int buf,
                                            const __nv_bfloat16* Wh,
                                            const __nv_bfloat16* Wl,
                                            int row_base, int chunk) {
    const uint32_t base = sb + SM_B + (uint32_t)buf * BBUF;
    #pragma unroll
    for (int i = 0; i < 2; ++i) {
        int idx = tid + i * 256;        // row*4 + seg, 512 total
        int row = idx >> 2, seg = idx & 3;
        uint32_t d = base + (uint32_t)(row * BROW + seg * 16);
        const int so = (row_base + row) * HH + chunk * 32 + seg * 8;
        cpa16(d, Wh + so);
        cpa16(d + BHALF, Wl + so);
    }
}

// ============================ main MLP kernel ===============================
// is_edge=1: X=[feat[from]|feat[to]] -> msg MLP -> atomicAdd into g_agg[to]
// is_edge=0: X=[g_agg[n]|feat[n]]    -> upd MLP -> out = feat + h
__global__ void __launch_bounds__(256, 2) mlp_kernel(
    int is_edge, const float* __restrict__ feat,
    const int* __restrict__ from_idx, const int* __restrict__ to_idx,
    const float* __restrict__ b0, const float* __restrict__ b1,
    float* __restrict__ outp)
{
    extern __shared__ char smc[];
    const uint32_t sb = smem_u32(smc);
    const int tid  = threadIdx.x;
    const int wid  = tid >> 5;
    const int lane = tid & 31;
    const int wr   = wid & 1;    // row group: rows wr*32..+32
    const int wc   = wid >> 1;   // col group (0..3)
    const int lrow = ((lane >> 3) & 1) * 8 + (lane & 7);
    const int lcol = (lane >> 4) * 8;

    float* b0s = reinterpret_cast<float*>(smc + SM_B0);
    float* b1s = reinterpret_cast<float*>(smc + SM_B1);
    int*   sfr = reinterpret_cast<int*>(smc + SM_FR);
    int*   sto = reinterpret_cast<int*>(smc + SM_TO);

    const int tile0 = blockIdx.x * TM;
    const int total = is_edge ? NE : NN;
    const int rem   = min(TM, total - tile0);

    b0s[tid] = b0[tid];
    if (tid < 128) b1s[tid] = b1[tid];
    if (is_edge && tid < 64) {
        int e = tile0 + tid;
        sfr[tid] = (tid < rem) ? from_idx[e] : 0;
        sto[tid] = (tid < rem) ? to_idx[e] : 0;
    }
    __syncthreads();

    const __nv_bfloat16* W0h = is_edge ? g_mW0h : g_uW0h;
    const __nv_bfloat16* W0l = is_edge ? g_mW0l : g_uW0l;
    const __nv_bfloat16* W1h = is_edge ? g_mW1h : g_uW1h;
    const __nv_bfloat16* W1l = is_edge ? g_mW1l : g_uW1l;

    // prologue: stage GEMM1 chunk g=0 (hidden behind the gather)
    stage_chunk(sb, tid, 0, W0h, W0l, 0, 0);
    CP_COMMIT();

    // ---- gather X [64 x 256] fp32 -> bf16 hi/lo into A tiles ---------------
    {
        const float4* f4 = reinterpret_cast<const float4*>(feat);
        const float4* a4 = reinterpret_cast<const float4*>(g_agg);
        #pragma unroll
        for (int it = 0; it < 16; ++it) {
            int ci = tid + it * 256;      // 0..4095
            int r  = ci >> 6;
            int c4 = ci & 63;
            float4 v = make_float4(0.f, 0.f, 0.f, 0.f);
            if (is_edge) {
                int src = (c4 < 32) ? sfr[r] : sto[r];
                v = f4[(size_t)src * 32 + (c4 & 31)];
            } else {
                int node = tile0 + r;
                if (node < NN)
                    v = (c4 < 32) ? a4[(size_t)node * 32 + c4]
                                  : f4[(size_t)node * 32 + (c4 - 32)];
            }
            __nv_bfloat16 h0 = __float2bfloat16(v.x), h1 = __float2bfloat16(v.y);
            __nv_bfloat16 h2 = __float2bfloat16(v.z), h3 = __float2bfloat16(v.w);
            uint2 H, L;
            H.x = pack_bf16(v.x, v.y);
            H.y = pack_bf16(v.z, v.w);
            L.x = pack_bf16(v.x - __bfloat162float(h0), v.y - __bfloat162float(h1));
            L.y = pack_bf16(v.z - __bfloat162float(h2), v.w - __bfloat162float(h3));
            int off = r * AROW + c4 * 8;
            *reinterpret_cast<uint2*>(smc + SM_AHI + off) = H;
            *reinterpret_cast<uint2*>(smc + SM_ALO + off) = L;
        }
    }
    __syncthreads();

    // ======================= GEMM1: H = relu(X@W0+b0) =======================
    // N=256 split into two 128-row halves; 16 chunks of (128 N-rows x 32 K)
    // warp tile 32x32 per half -> acc[2][8][4] across both halves
    float acc[2][8][4];
    #pragma unroll
    for (int m = 0; m < 2; ++m)
        #pragma unroll
        for (int n = 0; n < 8; ++n)
            #pragma unroll
            for (int q = 0; q < 4; ++q) acc[m][n][q] = 0.f;

    for (int g = 0; g < 16; ++g) {
        if (g < 15) {
            int gn = g + 1;
            stage_chunk(sb, tid, gn & 1, W0h, W0l, (gn >> 3) * 128, gn & 7);
        }
        CP_COMMIT();
        CP_WAIT(1);
        __syncthreads();
        const int nh = g >> 3, c = g & 7;
        const uint32_t bbase = sb + SM_B + (uint32_t)(g & 1) * BBUF;
        #pragma unroll
        for (int ks = 0; ks < 2; ++ks) {
            const int kA = c * 32 + ks * 16;
            uint32_t ah[2][4], al[2][4];
            #pragma unroll
            for (int mt = 0; mt < 2; ++mt) {
                uint32_t aaddr = sb + SM_AHI +
                    (uint32_t)((wr * 32 + mt * 16 + lrow) * AROW + (kA + lcol) * 2);
                ldsm_x4(ah[mt][0], ah[mt][1], ah[mt][2], ah[mt][3], aaddr);
                ldsm_x4(al[mt][0], al[mt][1], al[mt][2], al[mt][3],
                        aaddr + (SM_ALO - SM_AHI));
            }
            #pragma unroll
            for (int np = 0; np < 2; ++np) {
                uint32_t baddr = bbase +
                    (uint32_t)((wc * 32 + np * 16 + lrow) * BROW + (ks * 16 + lcol) * 2);
                uint32_t bh0, bh1, bh2, bh3, bl0, bl1, bl2, bl3;
                ldsm_x4(bh0, bh1, bh2, bh3, baddr);
                ldsm_x4(bl0, bl1, bl2, bl3, baddr + BHALF);
                const int nb = nh * 4 + np * 2;
                #pragma unroll
                for (int mt = 0; mt < 2; ++mt) {
                    mma_bf16(acc[mt][nb],     ah[mt], bh0, bh2);
                    mma_bf16(acc[mt][nb + 1], ah[mt], bh1, bh3);
                    mma_bf16(acc[mt][nb],     al[mt], bh0, bh2);
                    mma_bf16(acc[mt][nb + 1], al[mt], bh1, bh3);
                    mma_bf16(acc[mt][nb],     ah[mt], bl0, bl2);
                    mma_bf16(acc[mt][nb + 1], ah[mt], bl1, bl3);
                }
            }
        }
        __syncthreads();
    }

    // prologue for GEMM2 chunk0 (hidden behind epilogue1)
    stage_chunk(sb, tid, 0, W1h, W1l, 0, 0);
    CP_COMMIT();

    // ---- epilogue1: bias+relu, hi/lo split, write H back into A tiles ------
    #pragma unroll
    for (int mt = 0; mt < 2; ++mt)
        #pragma unroll
        for (int nt = 0; nt < 8; ++nt) {
            int nh = nt >> 2, np = (nt >> 1) & 1, pr = nt & 1;
            int cc = nh * 128 + wc * 32 + np * 16 + pr * 8 + 2 * (lane & 3);
            int r0 = wr * 32 + mt * 16 + (lane >> 2);
            float* d = acc[mt][nt];
            float v0 = fmaxf(d[0] + b0s[cc], 0.f), v1 = fmaxf(d[1] + b0s[cc + 1], 0.f);
            float v2 = fmaxf(d[2] + b0s[cc], 0.f), v3 = fmaxf(d[3] + b0s[cc + 1], 0.f);
            __nv_bfloat16 h0 = __float2bfloat16(v0), h1 = __float2bfloat16(v1);
            __nv_bfloat16 h2 = __float2bfloat16(v2), h3 = __float2bfloat16(v3);
            int o0 = r0 * AROW + cc * 2;
            int o1 = (r0 + 8) * AROW + cc * 2;
            *reinterpret_cast<uint32_t*>(smc + SM_AHI + o0) = pack_bf16(v0, v1);
            *reinterpret_cast<uint32_t*>(smc + SM_AHI + o1) = pack_bf16(v2, v3);
            *reinterpret_cast<uint32_t*>(smc + SM_ALO + o0) =
                pack_bf16(v0 - __bfloat162float(h0), v1 - __bfloat162float(h1));
            *reinterpret_cast<uint32_t*>(smc + SM_ALO + o1) =
                pack_bf16(v2 - __bfloat162float(h2), v3 - __bfloat162float(h3));
        }

    // ======================= GEMM2: M = relu(H@W1+b1) =======================
    // N=128, warp tile 32x32, acc2[2][4][4]
    float ac2[2][4][4];
    #pragma unroll
    for (int m = 0; m < 2; ++m)
        #pragma unroll
        for (int n = 0; n < 4; ++n)
            #pragma unroll
            for (int q = 0; q < 4; ++q) ac2[m][n][q] = 0.f;

    for (int c = 0; c < 8; ++c) {
        if (c < 7) stage_chunk(sb, tid, (c + 1) & 1, W1h, W1l, 0, c + 1);
        CP_COMMIT();
        CP_WAIT(1);
        __syncthreads();
        const uint32_t bbase = sb + SM_B + (uint32_t)(c & 1) * BBUF;
        #pragma unroll
        for (int ks = 0; ks < 2; ++ks) {
            const int kA = c * 32 + ks * 16;
            uint32_t ah[2][4], al[2][4];
            #pragma unroll
            for (int mt = 0; mt < 2; ++mt) {
                uint32_t aaddr = sb + SM_AHI +
                    (uint32_t)((wr * 32 + mt * 16 + lrow) * AROW + (kA + lcol) * 2);
                ldsm_x4(ah[mt][0], ah[mt][1], ah[mt][2], ah[mt][3], aaddr);
                ldsm_x4(al[mt][0], al[mt][1], al[mt][2], al[mt][3],
                        aaddr + (SM_ALO - SM_AHI));
            }
            #pragma unroll
            for (int np = 0; np < 2; ++np) {
                uint32_t baddr = bbase +
                    (uint32_t)((wc * 32 + np * 16 + lrow) * BROW + (ks * 16 + lcol) * 2);
                uint32_t bh0, bh1, bh2, bh3, bl0, bl1, bl2, bl3;
                ldsm_x4(bh0, bh1, bh2, bh3, baddr);
                ldsm_x4(bl0, bl1, bl2, bl3, baddr + BHALF);
                const int nb = np * 2;
                #pragma unroll
                for (int mt = 0; mt < 2; ++mt) {
                    mma_bf16(ac2[mt][nb],     ah[mt], bh0, bh2);
                    mma_bf16(ac2[mt][nb + 1], ah[mt], bh1, bh3);
                    mma_bf16(ac2[mt][nb],     al[mt], bh0, bh2);
                    mma_bf16(ac2[mt][nb + 1], al[mt], bh1, bh3);
                    mma_bf16(ac2[mt][nb],     ah[mt], bl0, bl2);
                    mma_bf16(ac2[mt][nb + 1], ah[mt], bl1, bl3);
                }
            }
        }
        __syncthreads();
    }

    // ---- epilogue2: bias+relu, scatter-atomic / residual store -------------
    #pragma unroll
    for (int mt = 0; mt < 2; ++mt)
        #pragma unroll
        for (int nt = 0; nt < 4; ++nt) {
            int np = nt >> 1, pr = nt & 1;
            int cc = wc * 32 + np * 16 + pr * 8 + 2 * (lane & 3);
            int r0 = wr * 32 + mt * 16 + (lane >> 2);
            int r1 = r0 + 8;
            float* d = ac2[mt][nt];
            float v0 = fmaxf(d[0] + b1s[cc], 0.f), v1 = fmaxf(d[1] + b1s[cc + 1], 0.f);
            float v2 = fmaxf(d[2] + b1s[cc], 0.f), v3 = fmaxf(d[3] + b1s[cc + 1], 0.f);
            if (is_edge) {
                if (r0 < rem) {
                    float* a = g_agg + (size_t)sto[r0] * DD + cc;
                    atomicAdd(a, v0);
                    atomicAdd(a + 1, v1);
                }
                if (r1 < rem) {
                    float* a = g_agg + (size_t)sto[r1] * DD + cc;
                    atomicAdd(a, v2);
                    atomicAdd(a + 1, v3);
                }
            } else {
                int n0 = tile0 + r0, n1 = tile0 + r1;
                if (n0 < NN) {
                    float2 f = *reinterpret_cast<const float2*>(feat + (size_t)n0 * DD + cc);
                    *reinterpret_cast<float2*>(outp + (size_t)n0 * DD + cc) =
                        make_float2(f.x + v0, f.y + v1);
                }
                if (n1 < NN) {
                    float2 f = *reinterpret_cast<const float2*>(feat + (size_t)n1 * DD + cc);
                    *reinterpret_cast<float2*>(outp + (size_t)n1 * DD + cc) =
                        make_float2(f.x + v2, f.y + v3);
                }
            }
        }
}

// ============================== host launch =================================
extern "C" void kernel_launch(void* const* d_in, const int* in_sizes, int n_in,
                              void* d_out, int out_size)
{
    const float* feat  = (const float*)d_in[0];
    const int*   f_idx = (const int*)  d_in[1];
    const int*   t_idx = (const int*)  d_in[2];
    const float* msgW0 = (const float*)d_in[3];
    const float* msgb0 = (const float*)d_in[4];
    const float* msgW1 = (const float*)d_in[5];
    const float* msgb1 = (const float*)d_in[6];
    const float* updW0 = (const float*)d_in[7];
    const float* updb0 = (const float*)d_in[8];
    const float* updW1 = (const float*)d_in[9];
    const float* updb1 = (const float*)d_in[10];
    float* out = (float*)d_out;

    cudaFuncSetAttribute(mlp_kernel, cudaFuncAttributeMaxDynamicSharedMemorySize, SMEM_TOTAL);

    conv_w_kernel<<<768, 256>>>(msgW0, updW0, msgW1, updW1);
    zero_agg_kernel<<<1024, 256>>>();

    const int edge_tiles = (NE + TM - 1) / TM;  // 9375
    const int node_tiles = (NN + TM - 1) / TM;  // 782
    mlp_kernel<<<edge_tiles, 256, SMEM_TOTAL>>>(1, feat, f_idx, t_idx, msgb0, msgb1, nullptr);
    mlp_kernel<<<node_tiles, 256, SMEM_TOTAL>>>(0, feat, f_idx, t_idx, updb0, updb1, out);
}

// round 7
// speedup vs baseline: 2.2664x; 2.2664x over previous
#include <cuda_runtime.h>
#include <cuda_bf16.h>
#include <cstdint>
#include <cstddef>

#define NN 50000
#define NE 600000
#define DD 128
#define HH 256
#define TM 128

// ============================ device scratch ================================
__device__ float g_agg[(size_t)NN * DD];
__device__ float g_PQ[(size_t)NN * 512];    // per-node [P|Q]: P=feat@W0a+b0, Q=feat@W0b
// weights transposed to [N][K] row-major, bf16 hi/lo split
__device__ __nv_bfloat16 g_c0h[512 * DD],  g_c0l[512 * DD];   // msg [W0a|W0b]^T : [512][128]
__device__ __nv_bfloat16 g_mW1h[DD * HH],  g_mW1l[DD * HH];   // msg W1^T: [128][256]
__device__ __nv_bfloat16 g_uW0h[HH * HH],  g_uW0l[HH * HH];   // upd W0^T: [256][256]
__device__ __nv_bfloat16 g_uW1h[DD * HH],  g_uW1l[DD * HH];   // upd W1^T: [128][256]

// ============================ PTX helpers ===================================
__device__ __forceinline__ uint32_t smem_u32(const void* p) {
    uint32_t a;
    asm("{ .reg .u64 t; cvta.to.shared.u64 t, %1; cvt.u32.u64 %0, t; }" : "=r"(a) : "l"(p));
    return a;
}
__device__ __forceinline__ void ldsm_x4(uint32_t& r0, uint32_t& r1, uint32_t& r2,
                                        uint32_t& r3, uint32_t addr) {
    asm volatile("ldmatrix.sync.aligned.m8n8.x4.shared.b16 {%0,%1,%2,%3}, [%4];"
                 : "=r"(r0), "=r"(r1), "=r"(r2), "=r"(r3) : "r"(addr));
}
__device__ __forceinline__ void mma_bf16(float* d, const uint32_t* a,
                                         uint32_t b0, uint32_t b1) {
    asm volatile(
        "mma.sync.aligned.m16n8k16.row.col.f32.bf16.bf16.f32 "
        "{%0,%1,%2,%3},{%4,%5,%6,%7},{%8,%9},{%0,%1,%2,%3};"
        : "+f"(d[0]), "+f"(d[1]), "+f"(d[2]), "+f"(d[3])
        : "r"(a[0]), "r"(a[1]), "r"(a[2]), "r"(a[3]), "r"(b0), "r"(b1));
}
__device__ __forceinline__ uint32_t pack_bf16(float a, float b) {
    __nv_bfloat162 t = __floats2bfloat162_rn(a, b);
    return *reinterpret_cast<uint32_t*>(&t);
}
__device__ __forceinline__ void cpa16(uint32_t dst, const void* src) {
    asm volatile("cp.async.cg.shared.global [%0], [%1], 16;"
                 :: "r"(dst), "l"(src) : "memory");
}
#define CP_COMMIT() asm volatile("cp.async.commit_group;" ::: "memory")
#define CP_WAIT(n)  asm volatile("cp.async.wait_group %0;" :: "n"(n) : "memory")

// store float4 -> hi/lo bf16x2 pairs at byte offset off in two tiles
__device__ __forceinline__ void split_store(char* smc, int hi_base, int lo_base,
                                            int off, float4 v) {
    __nv_bfloat16 h0 = __float2bfloat16(v.x), h1 = __float2bfloat16(v.y);
    __nv_bfloat16 h2 = __float2bfloat16(v.z), h3 = __float2bfloat16(v.w);
    uint2 H, L;
    H.x = pack_bf16(v.x, v.y);
    H.y = pack_bf16(v.z, v.w);
    L.x = pack_bf16(v.x - __bfloat162float(h0), v.y - __bfloat162float(h1));
    L.y = pack_bf16(v.z - __bfloat162float(h2), v.w - __bfloat162float(h3));
    *reinterpret_cast<uint2*>(smc + hi_base + off) = H;
    *reinterpret_cast<uint2*>(smc + lo_base + off) = L;
}

// =========================== prelude kernels ================================
__global__ void zero_agg_kernel() {
    const size_t n4 = (size_t)NN * DD / 4;
    float4 z = make_float4(0.f, 0.f, 0.f, 0.f);
    for (size_t i = (size_t)blockIdx.x * blockDim.x + threadIdx.x; i < n4;
         i += (size_t)gridDim.x * blockDim.x)
        reinterpret_cast<float4*>(g_agg)[i] = z;
}

__device__ __forceinline__ void put_split(__nv_bfloat16* h, __nv_bfloat16* l,
                                          int idx, float w) {
    __nv_bfloat16 hi = __float2bfloat16(w);
    h[idx] = hi;
    l[idx] = __float2bfloat16(w - __bfloat162float(hi));
}

__global__ void conv_w_kernel(const float* __restrict__ mW0, const float* __restrict__ uW0,
                              const float* __restrict__ mW1, const float* __restrict__ uW1) {
    int i = blockIdx.x * blockDim.x + threadIdx.x;
    if (i >= 196608) return;
    if (i < 65536) {
        // g_c0[n][k] (n<512,k<128): n<256 -> W0a^T = mW0[k][n]; n>=256 -> W0b^T = mW0[128+k][n-256]
        int n = i >> 7, k = i & 127;
        float w = (n < 256) ? mW0[k * HH + n] : mW0[(128 + k) * HH + (n - 256)];
        put_split(g_c0h, g_c0l, n * DD + k, w);
    } else if (i < 131072) {
        int j = i - 65536, k = j >> 8, n = j & 255;
        put_split(g_uW0h, g_uW0l, n * HH + k, uW0[j]);
    } else if (i < 163840) {
        int j = i - 131072, k = j >> 7, n = j & 127;
        put_split(g_mW1h, g_mW1l, n * HH + k, mW1[j]);
    } else {
        int j = i - 163840, k = j >> 7, n = j & 127;
        put_split(g_uW1h, g_uW1l, n * HH + k, uW1[j]);
    }
}

// generic B-chunk stager: nrows x 32 K-cols, BROW=80, 512 threads
__device__ __forceinline__ void stage_b(uint32_t bbase, int tid,
                                        const __nv_bfloat16* Wh,
                                        const __nv_bfloat16* Wl,
                                        int row_base, int chunk, int nrows,
                                        int kstride, int bhalf) {
    #pragma unroll
    for (int i = 0; i < 2; ++i) {
        int idx = tid + i * 512;
        if (idx < nrows * 4) {
            int row = idx >> 2, seg = idx & 3;
            uint32_t d = bbase + (uint32_t)(row * 80 + seg * 16);
            const int so = (row_base + row) * kstride + chunk * 32 + seg * 8;
            cpa16(d, Wh + so);
            cpa16(d + bhalf, Wl + so);
        }
    }
}

// ======================= PQ precompute kernel ===============================
// PQ[n][0:256] = feat[n] @ W0a + b0 ; PQ[n][256:512] = feat[n] @ W0b
// tile: 128 rows, K=128, N=512 done as two N=256 halves. 512 threads.
#define P_B0   0
#define P_AHI  4096
#define P_ALO  (4096 + 34816)           // 38912
#define P_B    (38912 + 34816)          // 73728
#define P_BHALF 20480
#define P_BBUF  40960
#define P_SMEM  (73728 + 2 * P_BBUF)    // 155648
#define AROW2  272

__global__ void __launch_bounds__(512, 1) pq_kernel(const float* __restrict__ feat,
                                                    const float* __restrict__ b0) {
    extern __shared__ char smc[];
    const uint32_t sb = smem_u32(smc);
    const int tid  = threadIdx.x;
    const int wid  = tid >> 5;
    const int lane = tid & 31;
    const int wr   = wid & 3;
    const int wc   = wid >> 2;
    const int lrow = ((lane >> 3) & 1) * 8 + (lane & 7);
    const int lcol = (lane >> 4) * 8;
    float* b0s = reinterpret_cast<float*>(smc + P_B0);

    const int tile0 = blockIdx.x * TM;
    if (tid < 256) b0s[tid] = b0[tid];

    // stage chunk g=0
    stage_b(sb + P_B, tid, g_c0h, g_c0l, 0, 0, 256, DD, P_BHALF);
    CP_COMMIT();

    // gather feat tile [128 x 128] -> hi/lo A tiles (AROW2)
    {
        const float4* f4 = reinterpret_cast<const float4*>(feat);
        #pragma unroll
        for (int it = 0; it < 8; ++it) {
            int ci = tid + it * 512;      // 0..4095
            int r  = ci >> 5;
            int c4 = ci & 31;
            int node = tile0 + r;
            float4 v = make_float4(0.f, 0.f, 0.f, 0.f);
            if (node < NN) v = f4[(size_t)node * 32 + c4];
            split_store(smc, P_AHI, P_ALO, r * AROW2 + c4 * 8, v);
        }
    }
    __syncthreads();

    for (int h = 0; h < 2; ++h) {
        float acc[2][8][4];
        #pragma unroll
        for (int m = 0; m < 2; ++m)
            #pragma unroll
            for (int n = 0; n < 8; ++n)
                #pragma unroll
                for (int q = 0; q < 4; ++q) acc[m][n][q] = 0.f;

        for (int c = 0; c < 4; ++c) {
            int g = h * 4 + c;
            if (g < 7)
                stage_b(sb + P_B + (uint32_t)((g + 1) & 1) * P_BBUF, tid,
                        g_c0h, g_c0l, ((g + 1) >> 2) * 256, (g + 1) & 3, 256, DD, P_BHALF);
            CP_COMMIT();
            CP_WAIT(1);
            __syncthreads();
            const uint32_t bbase = sb + P_B + (uint32_t)(g & 1) * P_BBUF;
            #pragma unroll
            for (int ks = 0; ks < 2; ++ks) {
                const int kA = c * 32 + ks * 16;
                uint32_t ah[2][4], al[2][4];
                #pragma unroll
                for (int mt = 0; mt < 2; ++mt) {
                    uint32_t aaddr = sb + P_AHI +
                        (uint32_t)((wr * 32 + mt * 16 + lrow) * AROW2 + (kA + lcol) * 2);
                    ldsm_x4(ah[mt][0], ah[mt][1], ah[mt][2], ah[mt][3], aaddr);
                    ldsm_x4(al[mt][0], al[mt][1], al[mt][2], al[mt][3],
                            aaddr + (P_ALO - P_AHI));
                }
                #pragma unroll
                for (int np = 0; np < 4; ++np) {
                    uint32_t baddr = bbase +
                        (uint32_t)((wc * 64 + np * 16 + lrow) * 80 + (ks * 16 + lcol) * 2);
                    uint32_t bh0, bh1, bh2, bh3, bl0, bl1, bl2, bl3;
                    ldsm_x4(bh0, bh1, bh2, bh3, baddr);
                    ldsm_x4(bl0, bl1, bl2, bl3, baddr + P_BHALF);
                    const int nb = np * 2;
                    #pragma unroll
                    for (int mt = 0; mt < 2; ++mt) {
                        mma_bf16(acc[mt][nb],     ah[mt], bh0, bh2);
                        mma_bf16(acc[mt][nb + 1], ah[mt], bh1, bh3);
                        mma_bf16(acc[mt][nb],     al[mt], bh0, bh2);
                        mma_bf16(acc[mt][nb + 1], al[mt], bh1, bh3);
                        mma_bf16(acc[mt][nb],     ah[mt], bl0, bl2);
                        mma_bf16(acc[mt][nb + 1], ah[mt], bl1, bl3);
                    }
                }
            }
            __syncthreads();
        }

        // epilogue: write PQ half h (P gets +b0)
        #pragma unroll
        for (int mt = 0; mt < 2; ++mt)
            #pragma unroll
            for (int nt = 0; nt < 8; ++nt) {
                int cc = wc * 64 + nt * 8 + 2 * (lane & 3);
                int r0 = wr * 32 + mt * 16 + (lane >> 2);
                int r1 = r0 + 8;
                float* d = acc[mt][nt];
                float bb0 = (h == 0) ? b0s[cc] : 0.f;
                float bb1 = (h == 0) ? b0s[cc + 1] : 0.f;
                int n0 = tile0 + r0, n1 = tile0 + r1;
                if (n0 < NN)
                    *reinterpret_cast<float2*>(g_PQ + (size_t)n0 * 512 + h * 256 + cc) =
                        make_float2(d[0] + bb0, d[1] + bb1);
                if (n1 < NN)
                    *reinterpret_cast<float2*>(g_PQ + (size_t)n1 * 512 + h * 256 + cc) =
                        make_float2(d[2] + bb0, d[3] + bb1);
            }
    }
}

// ============================ edge kernel ===================================
// H = relu(P[from] + Q[to]) ; M = relu(H @ W1 + b1) ; atomicAdd into g_agg[to]
#define E_B1   0
#define E_FR   512
#define E_TO   1024
#define E_AHI  4096
#define E_ALO  (4096 + 67584)           // 71680
#define E_B    (71680 + 67584)          // 139264
#define E_BHALF 10240
#define E_BBUF  20480
#define E_SMEM  (139264 + 2 * E_BBUF)   // 180224
#define AROW 528

__global__ void __launch_bounds__(512, 1) edge_kernel(
    const int* __restrict__ from_idx, const int* __restrict__ to_idx,
    const float* __restrict__ b1)
{
    extern __shared__ char smc[];
    const uint32_t sb = smem_u32(smc);
    const int tid  = threadIdx.x;
    const int wid  = tid >> 5;
    const int lane = tid & 31;
    const int wr   = wid & 3;
    const int wc   = wid >> 2;
    const int lrow = ((lane >> 3) & 1) * 8 + (lane & 7);
    const int lcol = (lane >> 4) * 8;

    float* b1s = reinterpret_cast<float*>(smc + E_B1);
    int*   sfr = reinterpret_cast<int*>(smc + E_FR);
    int*   sto = reinterpret_cast<int*>(smc + E_TO);

    const int tile0 = blockIdx.x * TM;
    const int rem   = min(TM, NE - tile0);

    if (tid < 128) b1s[tid] = b1[tid];
    if (tid >= 128 && tid < 256) {
        int t = tid - 128, e = tile0 + t;
        sfr[t] = (t < rem) ? from_idx[e] : 0;
        sto[t] = (t < rem) ? to_idx[e] : 0;
    }

    // stage W1 chunk0 (hidden behind gather)
    stage_b(sb + E_B, tid, g_mW1h, g_mW1l, 0, 0, 128, HH, E_BHALF);
    CP_COMMIT();
    __syncthreads();

    // ---- build H = relu(P[from] + Q[to]) -> hi/lo A tiles ------------------
    {
        const float4* pq4 = reinterpret_cast<const float4*>(g_PQ);
        #pragma unroll 4
        for (int it = 0; it < 16; ++it) {
            int ci = tid + it * 512;      // 0..8191
            int r  = ci >> 6;
            int c4 = ci & 63;
            float4 p = pq4[(size_t)sfr[r] * 128 + c4];
            float4 q = pq4[(size_t)sto[r] * 128 + 64 + c4];
            float4 v;
            v.x = fmaxf(p.x + q.x, 0.f);
            v.y = fmaxf(p.y + q.y, 0.f);
            v.z = fmaxf(p.z + q.z, 0.f);
            v.w = fmaxf(p.w + q.w, 0.f);
            split_store(smc, E_AHI, E_ALO, r * AROW + c4 * 8, v);
        }
    }
    __syncthreads();

    // ---- GEMM2: M = relu(H @ W1 + b1), warp tile 32x32 ---------------------
    float ac2[2][4][4];
    #pragma unroll
    for (int m = 0; m < 2; ++m)
        #pragma unroll
        for (int n = 0; n < 4; ++n)
            #pragma unroll
            for (int q = 0; q < 4; ++q) ac2[m][n][q] = 0.f;

    for (int c = 0; c < 8; ++c) {
        if (c < 7)
            stage_b(sb + E_B + (uint32_t)((c + 1) & 1) * E_BBUF, tid,
                    g_mW1h, g_mW1l, 0, c + 1, 128, HH, E_BHALF);
        CP_COMMIT();
        CP_WAIT(1);
        __syncthreads();
        const uint32_t bbase = sb + E_B + (uint32_t)(c & 1) * E_BBUF;
        #pragma unroll
        for (int ks = 0; ks < 2; ++ks) {
            const int kA = c * 32 + ks * 16;
            uint32_t ah[2][4], al[2][4];
            #pragma unroll
            for (int mt = 0; mt < 2; ++mt) {
                uint32_t aaddr = sb + E_AHI +
                    (uint32_t)((wr * 32 + mt * 16 + lrow) * AROW + (kA + lcol) * 2);
                ldsm_x4(ah[mt][0], ah[mt][1], ah[mt][2], ah[mt][3], aaddr);
                ldsm_x4(al[mt][0], al[mt][1], al[mt][2], al[mt][3],
                        aaddr + (E_ALO - E_AHI));
            }
            #pragma unroll
            for (int np = 0; np < 2; ++np) {
                uint32_t baddr = bbase +
                    (uint32_t)((wc * 32 + np * 16 + lrow) * 80 + (ks * 16 + lcol) * 2);
                uint32_t bh0, bh1, bh2, bh3, bl0, bl1, bl2, bl3;
                ldsm_x4(bh0, bh1, bh2, bh3, baddr);
                ldsm_x4(bl0, bl1, bl2, bl3, baddr + E_BHALF);
                const int nb = np * 2;
                #pragma unroll
                for (int mt = 0; mt < 2; ++mt) {
                    mma_bf16(ac2[mt][nb],     ah[mt], bh0, bh2);
                    mma_bf16(ac2[mt][nb + 1], ah[mt], bh1, bh3);
                    mma_bf16(ac2[mt][nb],     al[mt], bh0, bh2);
                    mma_bf16(ac2[mt][nb + 1], al[mt], bh1, bh3);
                    mma_bf16(ac2[mt][nb],     ah[mt], bl0, bl2);
                    mma_bf16(ac2[mt][nb + 1], ah[mt], bl1, bl3);
                }
            }
        }
        __syncthreads();
    }

    // ---- epilogue: bias+relu, scatter-atomic -------------------------------
    #pragma unroll
    for (int mt = 0; mt < 2; ++mt)
        #pragma unroll
        for (int nt = 0; nt < 4; ++nt) {
            int cc = wc * 32 + nt * 8 + 2 * (lane & 3);
            int r0 = wr * 32 + mt * 16 + (lane >> 2);
            int r1 = r0 + 8;
            float* d = ac2[mt][nt];
            float v0 = fmaxf(d[0] + b1s[cc], 0.f), v1 = fmaxf(d[1] + b1s[cc + 1], 0.f);
            float v2 = fmaxf(d[2] + b1s[cc], 0.f), v3 = fmaxf(d[3] + b1s[cc + 1], 0.f);
            if (r0 < rem) {
                float* a = g_agg + (size_t)sto[r0] * DD + cc;
                atomicAdd(a, v0);
                atomicAdd(a + 1, v1);
            }
            if (r1 < rem) {
                float* a = g_agg + (size_t)sto[r1] * DD + cc;
                atomicAdd(a, v2);
                atomicAdd(a + 1, v3);
            }
        }
}

// ============================ node kernel (round-5) =========================
#define SM_B0   0
#define SM_B1   1024
#define SM_AHI  4096
#define SM_ALO  (4096 + 67584)          // 71680
#define SM_B    (71680 + 67584)         // 139264
#define N_BHALF 20480
#define N_BBUF  40960
#define N_SMEM  (139264 + 2 * N_BBUF)   // 221184

__global__ void __launch_bounds__(512, 1) node_kernel(
    const float* __restrict__ feat,
    const float* __restrict__ b0, const float* __restrict__ b1,
    float* __restrict__ outp)
{
    extern __shared__ char smc[];
    const uint32_t sb = smem_u32(smc);
    const int tid  = threadIdx.x;
    const int wid  = tid >> 5;
    const int lane = tid & 31;
    const int wr   = wid & 3;
    const int wc   = wid >> 2;
    const int lrow = ((lane >> 3) & 1) * 8 + (lane & 7);
    const int lcol = (lane >> 4) * 8;

    float* b0s = reinterpret_cast<float*>(smc + SM_B0);
    float* b1s = reinterpret_cast<float*>(smc + SM_B1);

    const int tile0 = blockIdx.x * TM;

    if (tid < 256) b0s[tid] = b0[tid];
    if (tid >= 256 && tid < 384) b1s[tid - 256] = b1[tid - 256];

    stage_b(sb + SM_B, tid, g_uW0h, g_uW0l, 0, 0, 256, HH, N_BHALF);
    CP_COMMIT();
    __syncthreads();

    // gather [agg | feat]
    {
        const float4* f4 = reinterpret_cast<const float4*>(feat);
        const float4* a4 = reinterpret_cast<const float4*>(g_agg);
        #pragma unroll
        for (int it = 0; it < 16; ++it) {
            int ci = tid + it * 512;
            int r  = ci >> 6;
            int c4 = ci & 63;
            int node = tile0 + r;
            float4 v = make_float4(0.f, 0.f, 0.f, 0.f);
            if (node < NN)
                v = (c4 < 32) ? a4[(size_t)node * 32 + c4]
                              : f4[(size_t)node * 32 + (c4 - 32)];
            split_store(smc, SM_AHI, SM_ALO, r * AROW + c4 * 8, v);
        }
    }
    __syncthreads();

    // GEMM1
    float acc[2][8][4];
    #pragma unroll
    for (int m = 0; m < 2; ++m)
        #pragma unroll
        for (int n = 0; n < 8; ++n)
            #pragma unroll
            for (int q = 0; q < 4; ++q) acc[m][n][q] = 0.f;

    for (int c = 0; c < 8; ++c) {
        if (c < 7)
            stage_b(sb + SM_B + (uint32_t)((c + 1) & 1) * N_BBUF, tid,
                    g_uW0h, g_uW0l, 0, c + 1, 256, HH, N_BHALF);
        CP_COMMIT();
        CP_WAIT(1);
        __syncthreads();
        const uint32_t bbase = sb + SM_B + (uint32_t)(c & 1) * N_BBUF;
        #pragma unroll
        for (int ks = 0; ks < 2; ++ks) {
            const int kA = c * 32 + ks * 16;
            uint32_t ah[2][4], al[2][4];
            #pragma unroll
            for (int mt = 0; mt < 2; ++mt) {
                uint32_t aaddr = sb + SM_AHI +
                    (uint32_t)((wr * 32 + mt * 16 + lrow) * AROW + (kA + lcol) * 2);
                ldsm_x4(ah[mt][0], ah[mt][1], ah[mt][2], ah[mt][3], aaddr);
                ldsm_x4(al[mt][0], al[mt][1], al[mt][2], al[mt][3],
                        aaddr + (SM_ALO - SM_AHI));
            }
            #pragma unroll
            for (int np = 0; np < 4; ++np) {
                uint32_t baddr = bbase +
                    (uint32_t)((wc * 64 + np * 16 + lrow) * 80 + (ks * 16 + lcol) * 2);
                uint32_t bh0, bh1, bh2, bh3, bl0, bl1, bl2, bl3;
                ldsm_x4(bh0, bh1, bh2, bh3, baddr);
                ldsm_x4(bl0, bl1, bl2, bl3, baddr + N_BHALF);
                const int nb = np * 2;
                #pragma unroll
                for (int mt = 0; mt < 2; ++mt) {
                    mma_bf16(acc[mt][nb],     ah[mt], bh0, bh2);
                    mma_bf16(acc[mt][nb + 1], ah[mt], bh1, bh3);
                    mma_bf16(acc[mt][nb],     al[mt], bh0, bh2);
                    mma_bf16(acc[mt][nb + 1], al[mt], bh1, bh3);
                    mma_bf16(acc[mt][nb],     ah[mt], bl0, bl2);
                    mma_bf16(acc[mt][nb + 1], ah[mt], bl1, bl3);
                }
            }
        }
        __syncthreads();
    }

    stage_b(sb + SM_B, tid, g_uW1h, g_uW1l, 0, 0, 128, HH, N_BHALF);
    CP_COMMIT();

    // epilogue1: H back into A tiles
    #pragma unroll
    for (int mt = 0; mt < 2; ++mt)
        #pragma unroll
        for (int nt = 0; nt < 8; ++nt) {
            int cc = wc * 64 + nt * 8 + 2 * (lane & 3);
            int r0 = wr * 32 + mt * 16 + (lane >> 2);
            float* d = acc[mt][nt];
            float v0 = fmaxf(d[0] + b0s[cc], 0.f), v1 = fmaxf(d[1] + b0s[cc + 1], 0.f);
            float v2 = fmaxf(d[2] + b0s[cc], 0.f), v3 = fmaxf(d[3] + b0s[cc + 1], 0.f);
            __nv_bfloat16 h0 = __float2bfloat16(v0), h1 = __float2bfloat16(v1);
            __nv_bfloat16 h2 = __float2bfloat16(v2), h3 = __float2bfloat16(v3);
            int o0 = r0 * AROW + cc * 2;
            int o1 = (r0 + 8) * AROW + cc * 2;
            *reinterpret_cast<uint32_t*>(smc + SM_AHI + o0) = pack_bf16(v0, v1);
            *reinterpret_cast<uint32_t*>(smc + SM_AHI + o1) = pack_bf16(v2, v3);
            *reinterpret_cast<uint32_t*>(smc + SM_ALO + o0) =
                pack_bf16(v0 - __bfloat162float(h0), v1 - __bfloat162float(h1));
            *reinterpret_cast<uint32_t*>(smc + SM_ALO + o1) =
                pack_bf16(v2 - __bfloat162float(h2), v3 - __bfloat162float(h3));
        }

    // GEMM2
    float ac2[2][4][4];
    #pragma unroll
    for (int m = 0; m < 2; ++m)
        #pragma unroll
        for (int n = 0; n < 4; ++n)
            #pragma unroll
            for (int q = 0; q < 4; ++q) ac2[m][n][q] = 0.f;

    for (int c = 0; c < 8; ++c) {
        if (c < 7)
            stage_b(sb + SM_B + (uint32_t)((c + 1) & 1) * N_BBUF, tid,
                    g_uW1h, g_uW1l, 0, c + 1, 128, HH, N_BHALF);
        CP_COMMIT();
        CP_WAIT(1);
        __syncthreads();
        const uint32_t bbase = sb + SM_B + (uint32_t)(c & 1) * N_BBUF;
        #pragma unroll
        for (int ks = 0; ks < 2; ++ks) {
            const int kA = c * 32 + ks * 16;
            uint32_t ah[2][4], al[2][4];
            #pragma unroll
            for (int mt = 0; mt < 2; ++mt) {
                uint32_t aaddr = sb + SM_AHI +
                    (uint32_t)((wr * 32 + mt * 16 + lrow) * AROW + (kA + lcol) * 2);
                ldsm_x4(ah[mt][0], ah[mt][1], ah[mt][2], ah[mt][3], aaddr);
                ldsm_x4(al[mt][0], al[mt][1], al[mt][2], al[mt][3],
                        aaddr + (SM_ALO - SM_AHI));
            }
            #pragma unroll
            for (int np = 0; np < 2; ++np) {
                uint32_t baddr = bbase +
                    (uint32_t)((wc * 32 + np * 16 + lrow) * 80 + (ks * 16 + lcol) * 2);
                uint32_t bh0, bh1, bh2, bh3, bl0, bl1, bl2, bl3;
                ldsm_x4(bh0, bh1, bh2, bh3, baddr);
                ldsm_x4(bl0, bl1, bl2, bl3, baddr + N_BHALF);
                const int nb = np * 2;
                #pragma unroll
                for (int mt = 0; mt < 2; ++mt) {
                    mma_bf16(ac2[mt][nb],     ah[mt], bh0, bh2);
                    mma_bf16(ac2[mt][nb + 1], ah[mt], bh1, bh3);
                    mma_bf16(ac2[mt][nb],     al[mt], bh0, bh2);
                    mma_bf16(ac2[mt][nb + 1], al[mt], bh1, bh3);
                    mma_bf16(ac2[mt][nb],     ah[mt], bl0, bl2);
                    mma_bf16(ac2[mt][nb + 1], ah[mt], bl1, bl3);
                }
            }
        }
        __syncthreads();
    }

    // epilogue2: residual store
    #pragma unroll
    for (int mt = 0; mt < 2; ++mt)
        #pragma unroll
        for (int nt = 0; nt < 4; ++nt) {
            int cc = wc * 32 + nt * 8 + 2 * (lane & 3);
            int r0 = wr * 32 + mt * 16 + (lane >> 2);
            int r1 = r0 + 8;
            float* d = ac2[mt][nt];
            float v0 = fmaxf(d[0] + b1s[cc], 0.f), v1 = fmaxf(d[1] + b1s[cc + 1], 0.f);
            float v2 = fmaxf(d[2] + b1s[cc], 0.f), v3 = fmaxf(d[3] + b1s[cc + 1], 0.f);
            int n0 = tile0 + r0, n1 = tile0 + r1;
            if (n0 < NN) {
                float2 f = *reinterpret_cast<const float2*>(feat + (size_t)n0 * DD + cc);
                *reinterpret_cast<float2*>(outp + (size_t)n0 * DD + cc) =
                    make_float2(f.x + v0, f.y + v1);
            }
            if (n1 < NN) {
                float2 f = *reinterpret_cast<const float2*>(feat + (size_t)n1 * DD + cc);
                *reinterpret_cast<float2*>(outp + (size_t)n1 * DD + cc) =
                    make_float2(f.x + v2, f.y + v3);
            }
        }
}

// ============================== host launch =================================
extern "C" void kernel_launch(void* const* d_in, const int* in_sizes, int n_in,
                              void* d_out, int out_size)
{
    const float* feat  = (const float*)d_in[0];
    const int*   f_idx = (const int*)  d_in[1];
    const int*   t_idx = (const int*)  d_in[2];
    const float* msgW0 = (const float*)d_in[3];
    const float* msgb0 = (const float*)d_in[4];
    const float* msgW1 = (const float*)d_in[5];
    const float* msgb1 = (const float*)d_in[6];
    const float* updW0 = (const float*)d_in[7];
    const float* updb0 = (const float*)d_in[8];
    const float* updW1 = (const float*)d_in[9];
    const float* updb1 = (const float*)d_in[10];
    float* out = (float*)d_out;

    cudaFuncSetAttribute(pq_kernel,   cudaFuncAttributeMaxDynamicSharedMemorySize, P_SMEM);
    cudaFuncSetAttribute(edge_kernel, cudaFuncAttributeMaxDynamicSharedMemorySize, E_SMEM);
    cudaFuncSetAttribute(node_kernel, cudaFuncAttributeMaxDynamicSharedMemorySize, N_SMEM);

    conv_w_kernel<<<768, 256>>>(msgW0, updW0, msgW1, updW1);
    zero_agg_kernel<<<1024, 256>>>();

    const int pq_tiles   = (NN + TM - 1) / TM;  // 391
    const int edge_tiles = (NE + TM - 1) / TM;  // 4688
    const int node_tiles = (NN + TM - 1) / TM;  // 391

    pq_kernel<<<pq_tiles, 512, P_SMEM>>>(feat, msgb0);
    edge_kernel<<<edge_tiles, 512, E_SMEM>>>(f_idx, t_idx, msgb1);
    node_kernel<<<node_tiles, 512, N_SMEM>>>(feat, updb0, updb1, out);
}

// round 8
// speedup vs baseline: 2.6572x; 1.1725x over previous
#include <cuda_runtime.h>
#include <cuda_bf16.h>
#include <cstdint>
#include <cstddef>

#define NN 50000
#define NE 600000
#define DD 128
#define HH 256
#define TM 128

// ============================ device scratch ================================
__device__ float g_agg[(size_t)NN * DD];
__device__ float g_PQ[(size_t)NN * 512];    // per-node [P|Q]: P=feat@W0a+b0, Q=feat@W0b
// weights transposed to [N][K] row-major, bf16 hi/lo split
__device__ __nv_bfloat16 g_c0h[512 * DD],  g_c0l[512 * DD];   // msg [W0a|W0b]^T : [512][128]
__device__ __nv_bfloat16 g_mW1h[DD * HH],  g_mW1l[DD * HH];   // msg W1^T: [128][256]
__device__ __nv_bfloat16 g_uW0h[HH * HH],  g_uW0l[HH * HH];   // upd W0^T: [256][256]
__device__ __nv_bfloat16 g_uW1h[DD * HH],  g_uW1l[DD * HH];   // upd W1^T: [128][256]

// ============================ PTX helpers ===================================
__device__ __forceinline__ uint32_t smem_u32(const void* p) {
    uint32_t a;
    asm("{ .reg .u64 t; cvta.to.shared.u64 t, %1; cvt.u32.u64 %0, t; }" : "=r"(a) : "l"(p));
    return a;
}
__device__ __forceinline__ void ldsm_x4(uint32_t& r0, uint32_t& r1, uint32_t& r2,
                                        uint32_t& r3, uint32_t addr) {
    asm volatile("ldmatrix.sync.aligned.m8n8.x4.shared.b16 {%0,%1,%2,%3}, [%4];"
                 : "=r"(r0), "=r"(r1), "=r"(r2), "=r"(r3) : "r"(addr));
}
__device__ __forceinline__ void mma_bf16(float* d, const uint32_t* a,
                                         uint32_t b0, uint32_t b1) {
    asm volatile(
        "mma.sync.aligned.m16n8k16.row.col.f32.bf16.bf16.f32 "
        "{%0,%1,%2,%3},{%4,%5,%6,%7},{%8,%9},{%0,%1,%2,%3};"
        : "+f"(d[0]), "+f"(d[1]), "+f"(d[2]), "+f"(d[3])
        : "r"(a[0]), "r"(a[1]), "r"(a[2]), "r"(a[3]), "r"(b0), "r"(b1));
}
__device__ __forceinline__ uint32_t pack_bf16(float a, float b) {
    __nv_bfloat162 t = __floats2bfloat162_rn(a, b);
    return *reinterpret_cast<uint32_t*>(&t);
}
__device__ __forceinline__ void cpa16(uint32_t dst, const void* src) {
    asm volatile("cp.async.cg.shared.global [%0], [%1], 16;"
                 :: "r"(dst), "l"(src) : "memory");
}
#define CP_COMMIT() asm volatile("cp.async.commit_group;" ::: "memory")
#define CP_WAIT(n)  asm volatile("cp.async.wait_group %0;" :: "n"(n) : "memory")

// store float4 -> hi/lo bf16x2 pairs at byte offset off in two tiles
__device__ __forceinline__ void split_store(char* smc, int hi_base, int lo_base,
                                            int off, float4 v) {
    __nv_bfloat16 h0 = __float2bfloat16(v.x), h1 = __float2bfloat16(v.y);
    __nv_bfloat16 h2 = __float2bfloat16(v.z), h3 = __float2bfloat16(v.w);
    uint2 H, L;
    H.x = pack_bf16(v.x, v.y);
    H.y = pack_bf16(v.z, v.w);
    L.x = pack_bf16(v.x - __bfloat162float(h0), v.y - __bfloat162float(h1));
    L.y = pack_bf16(v.z - __bfloat162float(h2), v.w - __bfloat162float(h3));
    *reinterpret_cast<uint2*>(smc + hi_base + off) = H;
    *reinterpret_cast<uint2*>(smc + lo_base + off) = L;
}

__device__ __forceinline__ float4 relu_add4(float4 p, float4 q) {
    float4 v;
    v.x = fmaxf(p.x + q.x, 0.f);
    v.y = fmaxf(p.y + q.y, 0.f);
    v.z = fmaxf(p.z + q.z, 0.f);
    v.w = fmaxf(p.w + q.w, 0.f);
    return v;
}

// =========================== prelude kernels ================================
__global__ void zero_agg_kernel() {
    const size_t n4 = (size_t)NN * DD / 4;
    float4 z = make_float4(0.f, 0.f, 0.f, 0.f);
    for (size_t i = (size_t)blockIdx.x * blockDim.x + threadIdx.x; i < n4;
         i += (size_t)gridDim.x * blockDim.x)
        reinterpret_cast<float4*>(g_agg)[i] = z;
}

__device__ __forceinline__ void put_split(__nv_bfloat16* h, __nv_bfloat16* l,
                                          int idx, float w) {
    __nv_bfloat16 hi = __float2bfloat16(w);
    h[idx] = hi;
    l[idx] = __float2bfloat16(w - __bfloat162float(hi));
}

__global__ void conv_w_kernel(const float* __restrict__ mW0, const float* __restrict__ uW0,
                              const float* __restrict__ mW1, const float* __restrict__ uW1) {
    int i = blockIdx.x * blockDim.x + threadIdx.x;
    if (i >= 196608) return;
    if (i < 65536) {
        int n = i >> 7, k = i & 127;
        float w = (n < 256) ? mW0[k * HH + n] : mW0[(128 + k) * HH + (n - 256)];
        put_split(g_c0h, g_c0l, n * DD + k, w);
    } else if (i < 131072) {
        int j = i - 65536, k = j >> 8, n = j & 255;
        put_split(g_uW0h, g_uW0l, n * HH + k, uW0[j]);
    } else if (i < 163840) {
        int j = i - 131072, k = j >> 7, n = j & 127;
        put_split(g_mW1h, g_mW1l, n * HH + k, mW1[j]);
    } else {
        int j = i - 163840, k = j >> 7, n = j & 127;
        put_split(g_uW1h, g_uW1l, n * HH + k, uW1[j]);
    }
}

// generic B-chunk stager: nrows x 32 K-cols, BROW=80, 512 threads
__device__ __forceinline__ void stage_b(uint32_t bbase, int tid,
                                        const __nv_bfloat16* Wh,
                                        const __nv_bfloat16* Wl,
                                        int row_base, int chunk, int nrows,
                                        int kstride, int bhalf) {
    #pragma unroll
    for (int i = 0; i < 2; ++i) {
        int idx = tid + i * 512;
        if (idx < nrows * 4) {
            int row = idx >> 2, seg = idx & 3;
            uint32_t d = bbase + (uint32_t)(row * 80 + seg * 16);
            const int so = (row_base + row) * kstride + chunk * 32 + seg * 8;
            cpa16(d, Wh + so);
            cpa16(d + bhalf, Wl + so);
        }
    }
}

// ======================= PQ precompute kernel ===============================
#define P_B0   0
#define P_AHI  4096
#define P_ALO  (4096 + 34816)           // 38912
#define P_B    (38912 + 34816)          // 73728
#define P_BHALF 20480
#define P_BBUF  40960
#define P_SMEM  (73728 + 2 * P_BBUF)    // 155648
#define AROW2  272

__global__ void __launch_bounds__(512, 1) pq_kernel(const float* __restrict__ feat,
                                                    const float* __restrict__ b0) {
    extern __shared__ char smc[];
    const uint32_t sb = smem_u32(smc);
    const int tid  = threadIdx.x;
    const int wid  = tid >> 5;
    const int lane = tid & 31;
    const int wr   = wid & 3;
    const int wc   = wid >> 2;
    const int lrow = ((lane >> 3) & 1) * 8 + (lane & 7);
    const int lcol = (lane >> 4) * 8;
    float* b0s = reinterpret_cast<float*>(smc + P_B0);

    const int tile0 = blockIdx.x * TM;
    if (tid < 256) b0s[tid] = b0[tid];

    stage_b(sb + P_B, tid, g_c0h, g_c0l, 0, 0, 256, DD, P_BHALF);
    CP_COMMIT();

    {
        const float4* f4 = reinterpret_cast<const float4*>(feat);
        #pragma unroll
        for (int it = 0; it < 8; ++it) {
            int ci = tid + it * 512;
            int r  = ci >> 5;
            int c4 = ci & 31;
            int node = tile0 + r;
            float4 v = make_float4(0.f, 0.f, 0.f, 0.f);
            if (node < NN) v = f4[(size_t)node * 32 + c4];
            split_store(smc, P_AHI, P_ALO, r * AROW2 + c4 * 8, v);
        }
    }
    __syncthreads();

    for (int h = 0; h < 2; ++h) {
        float acc[2][8][4];
        #pragma unroll
        for (int m = 0; m < 2; ++m)
            #pragma unroll
            for (int n = 0; n < 8; ++n)
                #pragma unroll
                for (int q = 0; q < 4; ++q) acc[m][n][q] = 0.f;

        for (int c = 0; c < 4; ++c) {
            int g = h * 4 + c;
            if (g < 7)
                stage_b(sb + P_B + (uint32_t)((g + 1) & 1) * P_BBUF, tid,
                        g_c0h, g_c0l, ((g + 1) >> 2) * 256, (g + 1) & 3, 256, DD, P_BHALF);
            CP_COMMIT();
            CP_WAIT(1);
            __syncthreads();
            const uint32_t bbase = sb + P_B + (uint32_t)(g & 1) * P_BBUF;
            #pragma unroll
            for (int ks = 0; ks < 2; ++ks) {
                const int kA = c * 32 + ks * 16;
                uint32_t ah[2][4], al[2][4];
                #pragma unroll
                for (int mt = 0; mt < 2; ++mt) {
                    uint32_t aaddr = sb + P_AHI +
                        (uint32_t)((wr * 32 + mt * 16 + lrow) * AROW2 + (kA + lcol) * 2);
                    ldsm_x4(ah[mt][0], ah[mt][1], ah[mt][2], ah[mt][3], aaddr);
                    ldsm_x4(al[mt][0], al[mt][1], al[mt][2], al[mt][3],
                            aaddr + (P_ALO - P_AHI));
                }
                #pragma unroll
                for (int np = 0; np < 4; ++np) {
                    uint32_t baddr = bbase +
                        (uint32_t)((wc * 64 + np * 16 + lrow) * 80 + (ks * 16 + lcol) * 2);
                    uint32_t bh0, bh1, bh2, bh3, bl0, bl1, bl2, bl3;
                    ldsm_x4(bh0, bh1, bh2, bh3, baddr);
                    ldsm_x4(bl0, bl1, bl2, bl3, baddr + P_BHALF);
                    const int nb = np * 2;
                    #pragma unroll
                    for (int mt = 0; mt < 2; ++mt) {
                        mma_bf16(acc[mt][nb],     ah[mt], bh0, bh2);
                        mma_bf16(acc[mt][nb + 1], ah[mt], bh1, bh3);
                        mma_bf16(acc[mt][nb],     al[mt], bh0, bh2);
                        mma_bf16(acc[mt][nb + 1], al[mt], bh1, bh3);
                        mma_bf16(acc[mt][nb],     ah[mt], bl0, bl2);
                        mma_bf16(acc[mt][nb + 1], ah[mt], bl1, bl3);
                    }
                }
            }
            __syncthreads();
        }

        #pragma unroll
        for (int mt = 0; mt < 2; ++mt)
            #pragma unroll
            for (int nt = 0; nt < 8; ++nt) {
                int cc = wc * 64 + nt * 8 + 2 * (lane & 3);
                int r0 = wr * 32 + mt * 16 + (lane >> 2);
                int r1 = r0 + 8;
                float* d = acc[mt][nt];
                float bb0 = (h == 0) ? b0s[cc] : 0.f;
                float bb1 = (h == 0) ? b0s[cc + 1] : 0.f;
                int n0 = tile0 + r0, n1 = tile0 + r1;
                if (n0 < NN)
                    *reinterpret_cast<float2*>(g_PQ + (size_t)n0 * 512 + h * 256 + cc) =
                        make_float2(d[0] + bb0, d[1] + bb1);
                if (n1 < NN)
                    *reinterpret_cast<float2*>(g_PQ + (size_t)n1 * 512 + h * 256 + cc) =
                        make_float2(d[2] + bb0, d[3] + bb1);
            }
    }
}

// ============================ edge kernel (persistent) ======================
// H chunks = relu(P[from] + Q[to]) produced on the fly; W1 smem-resident.
#define E_B1   0                       // 128 floats
#define E_FR   512
#define E_TO   1024
#define E_A    4096                    // 2 A-chunk buffers: hi 10240 + lo 10240 each
#define E_B    (4096 + 40960)          // 45056; B hi: 8 chunks * 10240; lo at +81920
#define E_SMEM (45056 + 163840)        // 208896

#define EDGE_TILES ((NE + TM - 1) / TM)

__global__ void __launch_bounds__(512, 1) edge_kernel(
    const int* __restrict__ from_idx, const int* __restrict__ to_idx,
    const float* __restrict__ b1)
{
    extern __shared__ char smc[];
    const uint32_t sb = smem_u32(smc);
    const int tid  = threadIdx.x;
    const int wid  = tid >> 5;
    const int lane = tid & 31;
    const int wr   = wid & 3;
    const int wc   = wid >> 2;
    const int lrow = ((lane >> 3) & 1) * 8 + (lane & 7);
    const int lcol = (lane >> 4) * 8;

    float* b1s = reinterpret_cast<float*>(smc + E_B1);
    int*   sfr = reinterpret_cast<int*>(smc + E_FR);
    int*   sto = reinterpret_cast<int*>(smc + E_TO);

    if (tid < 128) b1s[tid] = b1[tid];

    // ---- stage resident W1 hi/lo once ----
    #pragma unroll
    for (int i = 0; i < 8; ++i) {
        int idx = tid + i * 512;          // c*512 + row*4 + seg
        int c = idx >> 9, rs = idx & 511;
        int row = rs >> 2, seg = rs & 3;
        uint32_t d = sb + E_B + (uint32_t)(c * 10240 + row * 80 + seg * 16);
        int so = row * HH + c * 32 + seg * 8;
        cpa16(d, g_mW1h + so);
        cpa16(d + 81920, g_mW1l + so);
    }
    CP_COMMIT();
    CP_WAIT(0);
    __syncthreads();

    const float4* pq4 = reinterpret_cast<const float4*>(g_PQ);
    const int r  = tid >> 2;              // 0..127 (row this thread produces)
    const int sg = tid & 3;               // seg: 2 float4 per seg

    for (int tile = blockIdx.x; tile < EDGE_TILES; tile += gridDim.x) {
        const int tile0 = tile * TM;
        const int rem   = min(TM, NE - tile0);

        __syncthreads();                  // prior epilogue readers of sto done
        if (tid < 128) {
            int e = tile0 + tid;
            sfr[tid] = (tid < rem) ? from_idx[e] : 0;
        } else if (tid < 256) {
            int t = tid - 128, e = tile0 + t;
            sto[t] = (t < rem) ? to_idx[e] : 0;
        }
        __syncthreads();

        const size_t prow = (size_t)sfr[r] * 128 + sg * 2;        // float4 units
        const size_t qrow = (size_t)sto[r] * 128 + 64 + sg * 2;

        // produce chunk 0 into buf 0
        {
            float4 p0 = pq4[prow], p1 = pq4[prow + 1];
            float4 q0 = pq4[qrow], q1 = pq4[qrow + 1];
            int off = r * 80 + sg * 16;
            split_store(smc, E_A, E_A + 10240, off,     relu_add4(p0, q0));
            split_store(smc, E_A, E_A + 10240, off + 8, relu_add4(p1, q1));
        }
        __syncthreads();

        float ac2[2][4][4];
        #pragma unroll
        for (int m = 0; m < 2; ++m)
            #pragma unroll
            for (int n = 0; n < 4; ++n)
                #pragma unroll
                for (int q = 0; q < 4; ++q) ac2[m][n][q] = 0.f;

        #pragma unroll
        for (int c = 0; c < 8; ++c) {
            // issue next chunk's gathers (latency hidden by MMA below)
            float4 p0, p1, q0, q1;
            if (c < 7) {
                p0 = pq4[prow + (c + 1) * 8];
                p1 = pq4[prow + (c + 1) * 8 + 1];
                q0 = pq4[qrow + (c + 1) * 8];
                q1 = pq4[qrow + (c + 1) * 8 + 1];
            }
            const uint32_t abase = sb + E_A + (uint32_t)((c & 1) * 20480);
            const uint32_t bbase = sb + E_B + (uint32_t)(c * 10240);
            #pragma unroll
            for (int ks = 0; ks < 2; ++ks) {
                uint32_t ah[2][4], al[2][4];
                #pragma unroll
                for (int mt = 0; mt < 2; ++mt) {
                    uint32_t aaddr = abase +
                        (uint32_t)((wr * 32 + mt * 16 + lrow) * 80 + (ks * 16 + lcol) * 2);
                    ldsm_x4(ah[mt][0], ah[mt][1], ah[mt][2], ah[mt][3], aaddr);
                    ldsm_x4(al[mt][0], al[mt][1], al[mt][2], al[mt][3], aaddr + 10240);
                }
                #pragma unroll
                for (int np = 0; np < 2; ++np) {
                    uint32_t baddr = bbase +
                        (uint32_t)((wc * 32 + np * 16 + lrow) * 80 + (ks * 16 + lcol) * 2);
                    uint32_t bh0, bh1, bh2, bh3, bl0, bl1, bl2, bl3;
                    ldsm_x4(bh0, bh1, bh2, bh3, baddr);
                    ldsm_x4(bl0, bl1, bl2, bl3, baddr + 81920);
                    const int nb = np * 2;
                    #pragma unroll
                    for (int mt = 0; mt < 2; ++mt) {
                        mma_bf16(ac2[mt][nb],     ah[mt], bh0, bh2);
                        mma_bf16(ac2[mt][nb + 1], ah[mt], bh1, bh3);
                        mma_bf16(ac2[mt][nb],     al[mt], bh0, bh2);
                        mma_bf16(ac2[mt][nb + 1], al[mt], bh1, bh3);
                        mma_bf16(ac2[mt][nb],     ah[mt], bl0, bl2);
                        mma_bf16(ac2[mt][nb + 1], ah[mt], bl1, bl3);
                    }
                }
            }
            // convert + store next chunk into the other buffer
            if (c < 7) {
                const int ab = E_A + ((c + 1) & 1) * 20480;
                int off = r * 80 + sg * 16;
                split_store(smc, ab, ab + 10240, off,     relu_add4(p0, q0));
                split_store(smc, ab, ab + 10240, off + 8, relu_add4(p1, q1));
            }
            __syncthreads();
        }

        // ---- epilogue: bias+relu, scatter-atomic ----
        #pragma unroll
        for (int mt = 0; mt < 2; ++mt)
            #pragma unroll
            for (int nt = 0; nt < 4; ++nt) {
                int cc = wc * 32 + nt * 8 + 2 * (lane & 3);
                int r0 = wr * 32 + mt * 16 + (lane >> 2);
                int r1 = r0 + 8;
                float* d = ac2[mt][nt];
                float v0 = fmaxf(d[0] + b1s[cc], 0.f), v1 = fmaxf(d[1] + b1s[cc + 1], 0.f);
                float v2 = fmaxf(d[2] + b1s[cc], 0.f), v3 = fmaxf(d[3] + b1s[cc + 1], 0.f);
                if (r0 < rem) {
                    float* a = g_agg + (size_t)sto[r0] * DD + cc;
                    atomicAdd(a, v0);
                    atomicAdd(a + 1, v1);
                }
                if (r1 < rem) {
                    float* a = g_agg + (size_t)sto[r1] * DD + cc;
                    atomicAdd(a, v2);
                    atomicAdd(a + 1, v3);
                }
            }
    }
}

// ============================ node kernel ===================================
#define SM_B0   0
#define SM_B1   1024
#define SM_AHI  4096
#define SM_ALO  (4096 + 67584)          // 71680
#define SM_B    (71680 + 67584)         // 139264
#define N_BHALF 20480
#define N_BBUF  40960
#define N_SMEM  (139264 + 2 * N_BBUF)   // 221184
#define AROW 528

__global__ void __launch_bounds__(512, 1) node_kernel(
    const float* __restrict__ feat,
    const float* __restrict__ b0, const float* __restrict__ b1,
    float* __restrict__ outp)
{
    extern __shared__ char smc[];
    const uint32_t sb = smem_u32(smc);
    const int tid  = threadIdx.x;
    const int wid  = tid >> 5;
    const int lane = tid & 31;
    const int wr   = wid & 3;
    const int wc   = wid >> 2;
    const int lrow = ((lane >> 3) & 1) * 8 + (lane & 7);
    const int lcol = (lane >> 4) * 8;

    float* b0s = reinterpret_cast<float*>(smc + SM_B0);
    float* b1s = reinterpret_cast<float*>(smc + SM_B1);

    const int tile0 = blockIdx.x * TM;

    if (tid < 256) b0s[tid] = b0[tid];
    if (tid >= 256 && tid < 384) b1s[tid - 256] = b1[tid - 256];

    stage_b(sb + SM_B, tid, g_uW0h, g_uW0l, 0, 0, 256, HH, N_BHALF);
    CP_COMMIT();
    __syncthreads();

    {
        const float4* f4 = reinterpret_cast<const float4*>(feat);
        const float4* a4 = reinterpret_cast<const float4*>(g_agg);
        #pragma unroll
        for (int it = 0; it < 16; ++it) {
            int ci = tid + it * 512;
            int r  = ci >> 6;
            int c4 = ci & 63;
            int node = tile0 + r;
            float4 v = make_float4(0.f, 0.f, 0.f, 0.f);
            if (node < NN)
                v = (c4 < 32) ? a4[(size_t)node * 32 + c4]
                              : f4[(size_t)node * 32 + (c4 - 32)];
            split_store(smc, SM_AHI, SM_ALO, r * AROW + c4 * 8, v);
        }
    }
    __syncthreads();

    float acc[2][8][4];
    #pragma unroll
    for (int m = 0; m < 2; ++m)
        #pragma unroll
        for (int n = 0; n < 8; ++n)
            #pragma unroll
            for (int q = 0; q < 4; ++q) acc[m][n][q] = 0.f;

    for (int c = 0; c < 8; ++c) {
        if (c < 7)
            stage_b(sb + SM_B + (uint32_t)((c + 1) & 1) * N_BBUF, tid,
                    g_uW0h, g_uW0l, 0, c + 1, 256, HH, N_BHALF);
        CP_COMMIT();
        CP_WAIT(1);
        __syncthreads();
        const uint32_t bbase = sb + SM_B + (uint32_t)(c & 1) * N_BBUF;
        #pragma unroll
        for (int ks = 0; ks < 2; ++ks) {
            const int kA = c * 32 + ks * 16;
            uint32_t ah[2][4], al[2][4];
            #pragma unroll
            for (int mt = 0; mt < 2; ++mt) {
                uint32_t aaddr = sb + SM_AHI +
                    (uint32_t)((wr * 32 + mt * 16 + lrow) * AROW + (kA + lcol) * 2);
                ldsm_x4(ah[mt][0], ah[mt][1], ah[mt][2], ah[mt][3], aaddr);
                ldsm_x4(al[mt][0], al[mt][1], al[mt][2], al[mt][3],
                        aaddr + (SM_ALO - SM_AHI));
            }
            #pragma unroll
            for (int np = 0; np < 4; ++np) {
                uint32_t baddr = bbase +
                    (uint32_t)((wc * 64 + np * 16 + lrow) * 80 + (ks * 16 + lcol) * 2);
                uint32_t bh0, bh1, bh2, bh3, bl0, bl1, bl2, bl3;
                ldsm_x4(bh0, bh1, bh2, bh3, baddr);
                ldsm_x4(bl0, bl1, bl2, bl3, baddr + N_BHALF);
                const int nb = np * 2;
                #pragma unroll
                for (int mt = 0; mt < 2; ++mt) {
                    mma_bf16(acc[mt][nb],     ah[mt], bh0, bh2);
                    mma_bf16(acc[mt][nb + 1], ah[mt], bh1, bh3);
                    mma_bf16(acc[mt][nb],     al[mt], bh0, bh2);
                    mma_bf16(acc[mt][nb + 1], al[mt], bh1, bh3);
                    mma_bf16(acc[mt][nb],     ah[mt], bl0, bl2);
                    mma_bf16(acc[mt][nb + 1], ah[mt], bl1, bl3);
                }
            }
        }
        __syncthreads();
    }

    stage_b(sb + SM_B, tid, g_uW1h, g_uW1l, 0, 0, 128, HH, N_BHALF);
    CP_COMMIT();

    #pragma unroll
    for (int mt = 0; mt < 2; ++mt)
        #pragma unroll
        for (int nt = 0; nt < 8; ++nt) {
            int cc = wc * 64 + nt * 8 + 2 * (lane & 3);
            int r0 = wr * 32 + mt * 16 + (lane >> 2);
            float* d = acc[mt][nt];
            float v0 = fmaxf(d[0] + b0s[cc], 0.f), v1 = fmaxf(d[1] + b0s[cc + 1], 0.f);
            float v2 = fmaxf(d[2] + b0s[cc], 0.f), v3 = fmaxf(d[3] + b0s[cc + 1], 0.f);
            __nv_bfloat16 h0 = __float2bfloat16(v0), h1 = __float2bfloat16(v1);
            __nv_bfloat16 h2 = __float2bfloat16(v2), h3 = __float2bfloat16(v3);
            int o0 = r0 * AROW + cc * 2;
            int o1 = (r0 + 8) * AROW + cc * 2;
            *reinterpret_cast<uint32_t*>(smc + SM_AHI + o0) = pack_bf16(v0, v1);
            *reinterpret_cast<uint32_t*>(smc + SM_AHI + o1) = pack_bf16(v2, v3);
            *reinterpret_cast<uint32_t*>(smc + SM_ALO + o0) =
                pack_bf16(v0 - __bfloat162float(h0), v1 - __bfloat162float(h1));
            *reinterpret_cast<uint32_t*>(smc + SM_ALO + o1) =
                pack_bf16(v2 - __bfloat162float(h2), v3 - __bfloat162float(h3));
        }

    float ac2[2][4][4];
    #pragma unroll
    for (int m = 0; m < 2; ++m)
        #pragma unroll
        for (int n = 0; n < 4; ++n)
            #pragma unroll
            for (int q = 0; q < 4; ++q) ac2[m][n][q] = 0.f;

    for (int c = 0; c < 8; ++c) {
        if (c < 7)
            stage_b(sb + SM_B + (uint32_t)((c + 1) & 1) * N_BBUF, tid,
                    g_uW1h, g_uW1l, 0, c + 1, 128, HH, N_BHALF);
        CP_COMMIT();
        CP_WAIT(1);
        __syncthreads();
        const uint32_t bbase = sb + SM_B + (uint32_t)(c & 1) * N_BBUF;
        #pragma unroll
        for (int ks = 0; ks < 2; ++ks) {
            const int kA = c * 32 + ks * 16;
            uint32_t ah[2][4], al[2][4];
            #pragma unroll
            for (int mt = 0; mt < 2; ++mt) {
                uint32_t aaddr = sb + SM_AHI +
                    (uint32_t)((wr * 32 + mt * 16 + lrow) * AROW + (kA + lcol) * 2);
                ldsm_x4(ah[mt][0], ah[mt][1], ah[mt][2], ah[mt][3], aaddr);
                ldsm_x4(al[mt][0], al[mt][1], al[mt][2], al[mt][3],
                        aaddr + (SM_ALO - SM_AHI));
            }
            #pragma unroll
            for (int np = 0; np < 2; ++np) {
                uint32_t baddr = bbase +
                    (uint32_t)((wc * 32 + np * 16 + lrow) * 80 + (ks * 16 + lcol) * 2);
                uint32_t bh0, bh1, bh2, bh3, bl0, bl1, bl2, bl3;
                ldsm_x4(bh0, bh1, bh2, bh3, baddr);
                ldsm_x4(bl0, bl1, bl2, bl3, baddr + N_BHALF);
                const int nb = np * 2;
                #pragma unroll
                for (int mt = 0; mt < 2; ++mt) {
                    mma_bf16(ac2[mt][nb],     ah[mt], bh0, bh2);
                    mma_bf16(ac2[mt][nb + 1], ah[mt], bh1, bh3);
                    mma_bf16(ac2[mt][nb],     al[mt], bh0, bh2);
                    mma_bf16(ac2[mt][nb + 1], al[mt], bh1, bh3);
                    mma_bf16(ac2[mt][nb],     ah[mt], bl0, bl2);
                    mma_bf16(ac2[mt][nb + 1], ah[mt], bl1, bl3);
                }
            }
        }
        __syncthreads();
    }

    #pragma unroll
    for (int mt = 0; mt < 2; ++mt)
        #pragma unroll
        for (int nt = 0; nt < 4; ++nt) {
            int cc = wc * 32 + nt * 8 + 2 * (lane & 3);
            int r0 = wr * 32 + mt * 16 + (lane >> 2);
            int r1 = r0 + 8;
            float* d = ac2[mt][nt];
            float v0 = fmaxf(d[0] + b1s[cc], 0.f), v1 = fmaxf(d[1] + b1s[cc + 1], 0.f);
            float v2 = fmaxf(d[2] + b1s[cc], 0.f), v3 = fmaxf(d[3] + b1s[cc + 1], 0.f);
            int n0 = tile0 + r0, n1 = tile0 + r1;
            if (n0 < NN) {
                float2 f = *reinterpret_cast<const float2*>(feat + (size_t)n0 * DD + cc);
                *reinterpret_cast<float2*>(outp + (size_t)n0 * DD + cc) =
                    make_float2(f.x + v0, f.y + v1);
            }
            if (n1 < NN) {
                float2 f = *reinterpret_cast<const float2*>(feat + (size_t)n1 * DD + cc);
                *reinterpret_cast<float2*>(outp + (size_t)n1 * DD + cc) =
                    make_float2(f.x + v2, f.y + v3);
            }
        }
}

// ============================== host launch =================================
extern "C" void kernel_launch(void* const* d_in, const int* in_sizes, int n_in,
                              void* d_out, int out_size)
{
    const float* feat  = (const float*)d_in[0];
    const int*   f_idx = (const int*)  d_in[1];
    const int*   t_idx = (const int*)  d_in[2];
    const float* msgW0 = (const float*)d_in[3];
    const float* msgb0 = (const float*)d_in[4];
    const float* msgW1 = (const float*)d_in[5];
    const float* msgb1 = (const float*)d_in[6];
    const float* updW0 = (const float*)d_in[7];
    const float* updb0 = (const float*)d_in[8];
    const float* updW1 = (const float*)d_in[9];
    const float* updb1 = (const float*)d_in[10];
    float* out = (float*)d_out;

    cudaFuncSetAttribute(pq_kernel,   cudaFuncAttributeMaxDynamicSharedMemorySize, P_SMEM);
    cudaFuncSetAttribute(edge_kernel, cudaFuncAttributeMaxDynamicSharedMemorySize, E_SMEM);
    cudaFuncSetAttribute(node_kernel, cudaFuncAttributeMaxDynamicSharedMemorySize, N_SMEM);

    conv_w_kernel<<<768, 256>>>(msgW0, updW0, msgW1, updW1);
    zero_agg_kernel<<<1024, 256>>>();

    const int pq_tiles   = (NN + TM - 1) / TM;  // 391
    const int node_tiles = (NN + TM - 1) / TM;  // 391

    pq_kernel<<<pq_tiles, 512, P_SMEM>>>(feat, msgb0);
    edge_kernel<<<152, 512, E_SMEM>>>(f_idx, t_idx, msgb1);
    node_kernel<<<node_tiles, 512, N_SMEM>>>(feat, updb0, updb1, out);
}